// round 1
// baseline (speedup 1.0000x reference)
#include <cuda_runtime.h>
#include <math.h>

#define BATCH  2
#define KPATCH 1600
#define DDIM   1024
#define CCLS   256
#define NBOX   32
#define PGRID  40
#define BN     (BATCH*NBOX)   /* 64 */
#define QSPLIT 4
#define DSPLIT 16             /* 1024/64 */

// ---------------- scratch (static device globals; no allocation) ----------------
__device__ float g_fninv[BATCH*KPATCH];     // 1/||feats[b,k,:]||
__device__ float g_eninv[CCLS];             // 1/||emb[c,:]||
__device__ float g_vy[BN*PGRID];            // per-box summed bicubic weights (y axis)
__device__ float g_vx[BN*PGRID];            // per-box summed bicubic weights (x axis)
__device__ int   g_rect[BN*4];              // p0,p1,q0,q1 nonzero tap rectangle
__device__ float g_cntinv[BN];              // 1/(box pixel count)
__device__ float g_Qpart[QSPLIT*BN*DDIM];   // partial weighted feature sums
__device__ float g_Opart[DSPLIT*BN*CCLS];   // partial output GEMM sums

// ---------------- kernel 1: row L2 norms of feats and embedding ----------------
__global__ void norm_kernel(const float* __restrict__ feats,
                            const float* __restrict__ emb) {
    int row = blockIdx.x;
    const float* p = (row < BATCH*KPATCH)
                       ? feats + (size_t)row * DDIM
                       : emb   + (size_t)(row - BATCH*KPATCH) * DDIM;
    int t = threadIdx.x;                       // 256 threads, 4 floats each
    float4 v = ((const float4*)p)[t];
    float ss = v.x*v.x + v.y*v.y + v.z*v.z + v.w*v.w;
    #pragma unroll
    for (int o = 16; o; o >>= 1) ss += __shfl_xor_sync(0xffffffffu, ss, o);
    __shared__ float ws[8];
    if ((t & 31) == 0) ws[t >> 5] = ss;
    __syncthreads();
    if (t == 0) {
        float s = ws[0]+ws[1]+ws[2]+ws[3]+ws[4]+ws[5]+ws[6]+ws[7];
        float inv = 1.0f / sqrtf(s);
        if (row < BATCH*KPATCH) g_fninv[row] = inv;
        else                    g_eninv[row - BATCH*KPATCH] = inv;
    }
}

// ---------------- kernel 2: per-box bicubic tap vectors -------------------------
// JAX bicubic: Keys cubic a=-0.5, sample_f = (y+0.5)/14 - 0.5, per-output
// normalization over valid taps. Computed in double to match JAX's f64 weights.
__device__ __forceinline__ double cubicd(double x) {   // x >= 0
    if (x >= 2.0) return 0.0;
    if (x >= 1.0) return ((-0.5*x + 2.5)*x - 4.0)*x + 2.0;
    return ((1.5*x - 2.5)*x)*x + 1.0;
}

__global__ void box_kernel(const int* __restrict__ boxes) {
    int bn = blockIdx.x;                       // 64 blocks, 80 threads
    int t  = threadIdx.x;
    int x_min = boxes[bn*4+0], y_min = boxes[bn*4+1];
    int x_max = boxes[bn*4+2], y_max = boxes[bn*4+3];

    int p, lo, hi;
    if (t < PGRID) { p = t;         lo = y_min; hi = y_max - 2; }
    else           { p = t - PGRID; lo = x_min; hi = x_max - 2; }

    double acc = 0.0;
    for (int y = lo; y <= hi; ++y) {
        double sf = (y + 0.5) / 14.0 - 0.5;
        double d  = fabs(sf - (double)p);
        if (d < 2.0) {
            int i0 = (int)floor(sf);
            double cs = 0.0;
            #pragma unroll
            for (int j = -1; j <= 2; ++j) {
                int ii = i0 + j;
                if (ii >= 0 && ii < PGRID) cs += cubicd(fabs(sf - (double)ii));
            }
            acc += cubicd(d) / cs;
        }
    }
    if (t < PGRID) g_vy[bn*PGRID + p] = (float)acc;
    else           g_vx[bn*PGRID + p] = (float)acc;

    if (t == 0) {
        double sfl = (y_min + 0.5) / 14.0 - 0.5;
        double sfh = (y_max - 2 + 0.5) / 14.0 - 0.5;
        int p0 = max(0, (int)floor(sfl) - 1);
        int p1 = min(PGRID - 1, (int)floor(sfh) + 2);
        sfl = (x_min + 0.5) / 14.0 - 0.5;
        sfh = (x_max - 2 + 0.5) / 14.0 - 0.5;
        int q0 = max(0, (int)floor(sfl) - 1);
        int q1 = min(PGRID - 1, (int)floor(sfh) + 2);
        g_rect[bn*4+0] = p0; g_rect[bn*4+1] = p1;
        g_rect[bn*4+2] = q0; g_rect[bn*4+3] = q1;
        long long cnt = (long long)(y_max - 1 - y_min) * (long long)(x_max - 1 - x_min);
        g_cntinv[bn] = 1.0f / (float)cnt;
    }
}

// ---------------- kernel 3: Q[bn,d] = sum_k w[bn,k]/fn[b,k] * feats[b,k,d] ------
// Only the nonzero tap rectangle is visited. p-range split QSPLIT ways for
// parallelism; partials written to g_Qpart.
__global__ void __launch_bounds__(256) q_kernel(const float* __restrict__ feats) {
    int s  = blockIdx.x;       // 0..QSPLIT-1
    int bn = blockIdx.y;       // 0..63
    int b  = bn >> 5;
    int p0 = g_rect[bn*4+0], p1 = g_rect[bn*4+1];
    int q0 = g_rect[bn*4+2], q1 = g_rect[bn*4+3];
    int np = p1 - p0 + 1;
    int plo = p0 + (np * s) / QSPLIT;
    int phi = p0 + (np * (s + 1)) / QSPLIT - 1;

    int t = threadIdx.x;       // 256 threads, float4 each -> D=1024
    float4 acc = make_float4(0.f, 0.f, 0.f, 0.f);
    const float4* f4 = (const float4*)feats;

    for (int p = plo; p <= phi; ++p) {
        float wy = g_vy[bn*PGRID + p];
        for (int q = q0; q <= q1; ++q) {
            int k = p * PGRID + q;
            float w = wy * g_vx[bn*PGRID + q] * g_fninv[b*KPATCH + k];
            float4 f = f4[(size_t)(b*KPATCH + k) * (DDIM/4) + t];
            acc.x += w * f.x; acc.y += w * f.y;
            acc.z += w * f.z; acc.w += w * f.w;
        }
    }
    ((float4*)g_Qpart)[(size_t)(s*BN + bn) * (DDIM/4) + t] = acc;
}

// ---------------- kernel 4: Opart = Q @ embT (64 x 1024 x 256, d-split) ---------
// Block = (32 classes) x (64 d). Loads emb tiles transposed via smem (coalesced
// along d), folds 1/en[c] in. Each thread: 1 class x 8 bn rows.
__global__ void __launch_bounds__(256) out_kernel(const float* __restrict__ emb) {
    __shared__ float Qs[BN * 64];      // [bn][dd]
    __shared__ float Es[64 * 33];      // [dd][c], padded
    int c0 = blockIdx.x * 32;
    int d0 = blockIdx.y * 64;
    int t  = threadIdx.x;

    #pragma unroll
    for (int i = 0; i < 16; ++i) {     // 4096 Q elems (sum QSPLIT partials)
        int lin = i * 256 + t;
        int bn = lin >> 6, dd = lin & 63;
        float v = 0.f;
        #pragma unroll
        for (int sp = 0; sp < QSPLIT; ++sp)
            v += g_Qpart[(sp*BN + bn) * DDIM + d0 + dd];
        Qs[bn*64 + dd] = v;
    }
    #pragma unroll
    for (int i = 0; i < 8; ++i) {      // 2048 emb elems, transposed into smem
        int lin = i * 256 + t;
        int c = lin >> 6, dd = lin & 63;
        Es[dd*33 + c] = emb[(size_t)(c0 + c) * DDIM + d0 + dd] * g_eninv[c0 + c];
    }
    __syncthreads();

    int c = t & 31, g = t >> 5;        // 8 bn-groups of 8
    float acc[8] = {0,0,0,0,0,0,0,0};
    for (int dd = 0; dd < 64; ++dd) {
        float e = Es[dd*33 + c];
        #pragma unroll
        for (int j = 0; j < 8; ++j)
            acc[j] += Qs[(g*8 + j)*64 + dd] * e;
    }
    #pragma unroll
    for (int j = 0; j < 8; ++j)
        g_Opart[(blockIdx.y*BN + g*8 + j) * CCLS + c0 + c] = acc[j];
}

// ---------------- kernel 5: reduce d-split partials, apply 1/count -------------
__global__ void oreduce_kernel(float* __restrict__ out) {
    int o  = blockIdx.x * 256 + threadIdx.x;   // 16384 outputs
    int bn = o >> 8;
    float s = 0.f;
    #pragma unroll
    for (int i = 0; i < DSPLIT; ++i) s += g_Opart[i*BN*CCLS + o];
    out[o] = s * g_cntinv[bn];
}

// ---------------- launch --------------------------------------------------------
extern "C" void kernel_launch(void* const* d_in, const int* in_sizes, int n_in,
                              void* d_out, int out_size) {
    (void)in_sizes; (void)n_in; (void)out_size;
    const float* feats = (const float*)d_in[0];
    const float* emb   = (const float*)d_in[1];
    const int*   boxes = (const int*)d_in[2];
    float* out = (float*)d_out;

    norm_kernel<<<BATCH*KPATCH + CCLS, 256>>>(feats, emb);
    box_kernel<<<BN, 80>>>(boxes);
    q_kernel<<<dim3(QSPLIT, BN), 256>>>(feats);
    out_kernel<<<dim3(CCLS/32, DDIM/64), 256>>>(emb);
    oreduce_kernel<<<BN, 256>>>(out);
}

// round 2
// speedup vs baseline: 19.4613x; 19.4613x over previous
#include <cuda_runtime.h>
#include <math.h>

#define BATCH  2
#define KPATCH 1600
#define DDIM   1024
#define CCLS   256
#define NBOX   32
#define PGRID  40
#define TARGET 560
#define BN     (BATCH*NBOX)            /* 64 */
#define NROWS  (BATCH*KPATCH + CCLS)   /* 3456 norm rows */
#define QSPLIT 4
#define DSPLIT 16                      /* 1024/64 */

// ---------------- scratch (static device globals; no allocation) ----------------
__device__ float g_fninv[BATCH*KPATCH];     // 1/||feats[b,k,:]||
__device__ float g_eninv[CCLS];             // 1/||emb[c,:]||
__device__ float g_W[PGRID*TARGET];         // bicubic weights, [p][y] layout
__device__ float g_vy[BN*PGRID];            // per-box summed weights (y axis)
__device__ float g_vx[BN*PGRID];            // per-box summed weights (x axis)
__device__ int   g_rect[BN*4];              // p0,p1,q0,q1 nonzero tap rectangle
__device__ float g_cntinv[BN];              // 1/(box pixel count)
__device__ float g_Qpart[QSPLIT*BN*DDIM];   // partial weighted feature sums
__device__ float g_Opart[DSPLIT*BN*CCLS];   // partial output GEMM sums

// Keys cubic, a = -0.5 (matches jax.image.resize 'bicubic'), fp32
__device__ __forceinline__ float cubicf(float x) {   // x >= 0
    if (x < 1.f) return ((1.5f*x - 2.5f)*x)*x + 1.f;
    if (x < 2.f) return ((-0.5f*x + 2.5f)*x - 4.f)*x + 2.f;
    return 0.f;
}

// ---------------- kernel 1: row L2 norms + bicubic weight table ----------------
__global__ void normw_kernel(const float* __restrict__ feats,
                             const float* __restrict__ emb) {
    int blk = blockIdx.x;
    int t = threadIdx.x;
    if (blk < NROWS) {
        const float* p = (blk < BATCH*KPATCH)
                           ? feats + (size_t)blk * DDIM
                           : emb   + (size_t)(blk - BATCH*KPATCH) * DDIM;
        float4 v = ((const float4*)p)[t];
        float ss = v.x*v.x + v.y*v.y + v.z*v.z + v.w*v.w;
        #pragma unroll
        for (int o = 16; o; o >>= 1) ss += __shfl_xor_sync(0xffffffffu, ss, o);
        __shared__ float ws[8];
        if ((t & 31) == 0) ws[t >> 5] = ss;
        __syncthreads();
        if (t == 0) {
            float s = ws[0]+ws[1]+ws[2]+ws[3]+ws[4]+ws[5]+ws[6]+ws[7];
            float inv = 1.0f / sqrtf(s);
            if (blk < BATCH*KPATCH) g_fninv[blk] = inv;
            else                    g_eninv[blk - BATCH*KPATCH] = inv;
        }
    } else {
        // weight table column p: W[y][p] normalized over valid taps
        int p = blk - NROWS;
        for (int y = t; y < TARGET; y += 256) {
            float sf = (y + 0.5f) * (1.0f/14.0f) - 0.5f;
            int i0 = (int)floorf(sf);
            float cs = 0.f;
            #pragma unroll
            for (int j = -1; j <= 2; ++j) {
                int ii = i0 + j;
                if (ii >= 0 && ii < PGRID) cs += cubicf(fabsf(sf - (float)ii));
            }
            float d = fabsf(sf - (float)p);
            float w = (d < 2.f) ? cubicf(d) / cs : 0.f;
            g_W[p*TARGET + y] = w;
        }
    }
}

// ---------------- kernel 2: per-box tap vectors from the table ------------------
__global__ void box_kernel(const int* __restrict__ boxes) {
    int bn = blockIdx.x;                       // 64 blocks, 80 threads
    int t  = threadIdx.x;
    int x_min = boxes[bn*4+0], y_min = boxes[bn*4+1];
    int x_max = boxes[bn*4+2], y_max = boxes[bn*4+3];

    if (t < 2*PGRID) {
        int p, lo, hi;
        if (t < PGRID) { p = t;         lo = y_min; hi = y_max - 2; }
        else           { p = t - PGRID; lo = x_min; hi = x_max - 2; }
        const float* col = g_W + p*TARGET;
        float acc = 0.f;
        #pragma unroll 8
        for (int y = lo; y <= hi; ++y) acc += col[y];
        if (t < PGRID) g_vy[bn*PGRID + p] = acc;
        else           g_vx[bn*PGRID + p] = acc;
    }

    if (t == 0) {
        float sfl = (y_min + 0.5f) * (1.0f/14.0f) - 0.5f;
        float sfh = (y_max - 2 + 0.5f) * (1.0f/14.0f) - 0.5f;
        int p0 = max(0, (int)floorf(sfl) - 1);
        int p1 = min(PGRID - 1, (int)floorf(sfh) + 2);
        sfl = (x_min + 0.5f) * (1.0f/14.0f) - 0.5f;
        sfh = (x_max - 2 + 0.5f) * (1.0f/14.0f) - 0.5f;
        int q0 = max(0, (int)floorf(sfl) - 1);
        int q1 = min(PGRID - 1, (int)floorf(sfh) + 2);
        g_rect[bn*4+0] = p0; g_rect[bn*4+1] = p1;
        g_rect[bn*4+2] = q0; g_rect[bn*4+3] = q1;
        float cnt = (float)((y_max - 1 - y_min) * (x_max - 1 - x_min));
        g_cntinv[bn] = 1.0f / cnt;
    }
}

// ---------------- kernel 3: Q[bn,d] = sum_k w[bn,k]/fn[b,k] * feats[b,k,d] ------
// Inner q loop padded to fixed 16 taps (max possible) and fully unrolled for MLP.
__global__ void __launch_bounds__(256) q_kernel(const float* __restrict__ feats) {
    int s  = blockIdx.x;       // 0..QSPLIT-1
    int bn = blockIdx.y;       // 0..63
    int b  = bn >> 5;
    int t  = threadIdx.x;

    __shared__ int   rect[4];
    __shared__ float vxs[16];
    if (t < 4) rect[t] = g_rect[bn*4+t];
    __syncthreads();
    int p0 = rect[0], p1 = rect[1], q0 = rect[2], q1 = rect[3];
    int nq = q1 - q0 + 1;      // <= 15
    if (t < 16) vxs[t] = (t < nq) ? g_vx[bn*PGRID + q0 + t] : 0.f;
    __syncthreads();

    int np  = p1 - p0 + 1;
    int plo = p0 + (np * s) / QSPLIT;
    int phi = p0 + (np * (s + 1)) / QSPLIT - 1;

    float4 acc = make_float4(0.f, 0.f, 0.f, 0.f);
    const float4* f4 = (const float4*)feats;

    for (int p = plo; p <= phi; ++p) {
        float wy = g_vy[bn*PGRID + p];
        int kbase = b*KPATCH + p*PGRID + q0;
        #pragma unroll
        for (int j = 0; j < 16; ++j) {
            int jj = min(j, nq - 1);                  // clamp address, weight is 0
            float w = wy * vxs[j] * g_fninv[kbase + jj];
            float4 f = f4[(size_t)(kbase + jj) * (DDIM/4) + t];
            acc.x += w * f.x; acc.y += w * f.y;
            acc.z += w * f.z; acc.w += w * f.w;
        }
    }
    ((float4*)g_Qpart)[(size_t)(s*BN + bn) * (DDIM/4) + t] = acc;
}

// ---------------- kernel 4: Opart = Q @ embT (64 x 1024 x 256, d-split) ---------
__global__ void __launch_bounds__(256) out_kernel(const float* __restrict__ emb) {
    __shared__ float Qs[BN * 64];      // [bn][dd]
    __shared__ float Es[64 * 33];      // [dd][c], padded
    int c0 = blockIdx.x * 32;
    int d0 = blockIdx.y * 64;
    int t  = threadIdx.x;

    #pragma unroll
    for (int i = 0; i < 16; ++i) {     // 4096 Q elems (sum QSPLIT partials)
        int lin = i * 256 + t;
        int bn = lin >> 6, dd = lin & 63;
        float v = 0.f;
        #pragma unroll
        for (int sp = 0; sp < QSPLIT; ++sp)
            v += g_Qpart[(sp*BN + bn) * DDIM + d0 + dd];
        Qs[bn*64 + dd] = v;
    }
    #pragma unroll
    for (int i = 0; i < 8; ++i) {      // 2048 emb elems, transposed into smem
        int lin = i * 256 + t;
        int c = lin >> 6, dd = lin & 63;
        Es[dd*33 + c] = emb[(size_t)(c0 + c) * DDIM + d0 + dd] * g_eninv[c0 + c];
    }
    __syncthreads();

    int c = t & 31, g = t >> 5;        // 8 bn-groups of 8
    float acc[8] = {0,0,0,0,0,0,0,0};
    for (int dd = 0; dd < 64; ++dd) {
        float e = Es[dd*33 + c];
        #pragma unroll
        for (int j = 0; j < 8; ++j)
            acc[j] += Qs[(g*8 + j)*64 + dd] * e;
    }
    #pragma unroll
    for (int j = 0; j < 8; ++j)
        g_Opart[(blockIdx.y*BN + g*8 + j) * CCLS + c0 + c] = acc[j];
}

// ---------------- kernel 5: reduce d-split partials, apply 1/count -------------
__global__ void oreduce_kernel(float* __restrict__ out) {
    int o  = blockIdx.x * 256 + threadIdx.x;   // 16384 outputs
    int bn = o >> 8;
    float s = 0.f;
    #pragma unroll
    for (int i = 0; i < DSPLIT; ++i) s += g_Opart[i*BN*CCLS + o];
    out[o] = s * g_cntinv[bn];
}

// ---------------- launch --------------------------------------------------------
extern "C" void kernel_launch(void* const* d_in, const int* in_sizes, int n_in,
                              void* d_out, int out_size) {
    (void)in_sizes; (void)n_in; (void)out_size;
    const float* feats = (const float*)d_in[0];
    const float* emb   = (const float*)d_in[1];
    const int*   boxes = (const int*)d_in[2];
    float* out = (float*)d_out;

    normw_kernel<<<NROWS + PGRID, 256>>>(feats, emb);
    box_kernel<<<BN, 80>>>(boxes);
    q_kernel<<<dim3(QSPLIT, BN), 256>>>(feats);
    out_kernel<<<dim3(CCLS/32, DDIM/64), 256>>>(emb);
    oreduce_kernel<<<BN, 256>>>(out);
}